// round 9
// baseline (speedup 1.0000x reference)
#include <cuda_runtime.h>
#include <cuda_fp16.h>

// Problem constants
#define N_NODES 50000
#define N_EDGES 1600000
#define E_TOT   (N_EDGES + N_NODES)
#define FDIM    128
#define NHEAD   2
#define NEG_SLOPE 0.2f

#define SCAN_BLK 1024
#define SCAN_NBLK ((N_NODES + SCAN_BLK - 1) / SCAN_BLK)   // 49

// ---------------- device scratch ----------------
__device__ int g_is64;
__device__ int g_src[N_EDGES];
__device__ int g_dst[N_EDGES];
__device__ int g_counts[N_NODES];
__device__ int g_rowptr[N_NODES + 1];
__device__ int g_fill[N_NODES];
__device__ __align__(16) int g_col[E_TOT];
__device__ int g_partials[64];
__device__ __align__(16) __half g_h16[(size_t)N_NODES * FDIM];   // fp16 features
__device__ __align__(16) float  g_x[(size_t)N_NODES * FDIM];     // fp32 layer output
__device__ __align__(16) float  g_esrc[N_NODES * NHEAD];         // [n][2] -> float2
__device__ __align__(16) float  g_edst[N_NODES * NHEAD];

// ---------------- packed f32x2 helpers ----------------
#define FMA2(d, a, b, c) \
    asm("fma.rn.f32x2 %0, %1, %2, %3;" : "=l"(d) : "l"(a), "l"(b), "l"(c))
#define PACK2(d, x) \
    asm("mov.b64 %0, {%1, %1};" : "=l"(d) : "r"(__float_as_uint(x)))
#define UNPACK2(lo, hi, v) \
    do { unsigned _l, _h; \
         asm("mov.b64 {%0, %1}, %2;" : "=r"(_l), "=r"(_h) : "l"(v)); \
         lo = __uint_as_float(_l); hi = __uint_as_float(_h); } while (0)

// ---------------- CSR build ----------------
__global__ void k_init_detect(const long long* ei) {
    int i = blockIdx.x * blockDim.x + threadIdx.x;
    if (i < N_NODES) g_counts[i] = 1;   // self loop
    if (i == 0) {
        int ok = 1;
        for (int t = 0; t < 16; t++) {
            long long v = ei[t];
            if (v < 0 || v >= (long long)N_NODES) { ok = 0; break; }
        }
        g_is64 = ok;
    }
}

__global__ void k_convert_hist(const void* eiv) {
    int e = blockIdx.x * blockDim.x + threadIdx.x;
    if (e >= N_EDGES) return;
    int s, d;
    if (g_is64) {
        const long long* p = (const long long*)eiv;
        s = (int)p[e];
        d = (int)p[N_EDGES + e];
    } else {
        const int* p = (const int*)eiv;
        s = p[e];
        d = p[N_EDGES + e];
    }
    g_src[e] = s;
    g_dst[e] = d;
    atomicAdd(&g_counts[d], 1);
}

__global__ void k_scan1() {
    __shared__ int sh[SCAN_BLK];
    int i = blockIdx.x * SCAN_BLK + threadIdx.x;
    int v = (i < N_NODES) ? g_counts[i] : 0;
    sh[threadIdx.x] = v;
    __syncthreads();
    for (int o = 1; o < SCAN_BLK; o <<= 1) {
        int t = 0;
        if ((int)threadIdx.x >= o) t = sh[threadIdx.x - o];
        __syncthreads();
        sh[threadIdx.x] += t;
        __syncthreads();
    }
    if (i < N_NODES) g_rowptr[i] = sh[threadIdx.x] - v;   // block-local exclusive
    if (threadIdx.x == SCAN_BLK - 1) g_partials[blockIdx.x] = sh[SCAN_BLK - 1];
}

__global__ void k_scan3_selfloop() {
    __shared__ int sh[64];
    if (threadIdx.x < 64)
        sh[threadIdx.x] = ((int)threadIdx.x < SCAN_NBLK) ? g_partials[threadIdx.x] : 0;
    __syncthreads();
    for (int o = 1; o < 64; o <<= 1) {
        int t = 0;
        if (threadIdx.x < 64 && (int)threadIdx.x >= o) t = sh[threadIdx.x - o];
        __syncthreads();
        if (threadIdx.x < 64) sh[threadIdx.x] += t;
        __syncthreads();
    }
    int blockOff = (blockIdx.x == 0) ? 0 : sh[blockIdx.x - 1];
    int i = blockIdx.x * SCAN_BLK + threadIdx.x;
    if (i < N_NODES) {
        int rp = g_rowptr[i] + blockOff;
        g_rowptr[i] = rp;
        g_col[rp] = i;      // self loop in slot 0
        g_fill[i] = 1;
    }
    if (i == 0) g_rowptr[N_NODES] = E_TOT;
}

__global__ void k_scatter() {
    int e = blockIdx.x * blockDim.x + threadIdx.x;
    if (e >= N_EDGES) return;
    int d = g_dst[e];
    int pos = g_rowptr[d] + atomicAdd(&g_fill[d], 1);
    g_col[pos] = g_src[e];
}

// ---------------- SGEMM (f32x2, BK=16) + fused logits, fp16 output ---------
__global__ __launch_bounds__(256, 2) void k_sgemm_fused(
    const float* __restrict__ A, const float* __restrict__ B,
    __half* __restrict__ C16,
    const float* __restrict__ a_src, const float* __restrict__ a_dst, int M) {
    __shared__ float As[16][128];   // transposed: As[k][m]
    __shared__ float Bs[16][128];

    const int tid  = threadIdx.x;
    const int row0 = blockIdx.x * 128;
    const int tr   = tid >> 4;
    const int tc   = tid & 15;

    const int laRow = tid >> 1;          // 0..127
    const int laCol = (tid & 1) * 8;     // 0 or 8
    const int lbRow = tid >> 4;          // 0..15
    const int lbCol = (tid & 15) * 8;    // 0..120

    unsigned long long acc[8][4];
#pragma unroll
    for (int i = 0; i < 8; i++)
#pragma unroll
        for (int p = 0; p < 4; p++) acc[i][p] = 0ull;

    for (int k0 = 0; k0 < 128; k0 += 16) {
        float4 av0 = make_float4(0.f, 0.f, 0.f, 0.f);
        float4 av1 = make_float4(0.f, 0.f, 0.f, 0.f);
        int arow = row0 + laRow;
        if (arow < M) {
            av0 = *(const float4*)&A[(size_t)arow * 128 + k0 + laCol];
            av1 = *(const float4*)&A[(size_t)arow * 128 + k0 + laCol + 4];
        }
        As[laCol + 0][laRow] = av0.x;
        As[laCol + 1][laRow] = av0.y;
        As[laCol + 2][laRow] = av0.z;
        As[laCol + 3][laRow] = av0.w;
        As[laCol + 4][laRow] = av1.x;
        As[laCol + 5][laRow] = av1.y;
        As[laCol + 6][laRow] = av1.z;
        As[laCol + 7][laRow] = av1.w;

        *(float4*)&Bs[lbRow][lbCol]     = *(const float4*)&B[(k0 + lbRow) * 128 + lbCol];
        *(float4*)&Bs[lbRow][lbCol + 4] = *(const float4*)&B[(k0 + lbRow) * 128 + lbCol + 4];
        __syncthreads();

#pragma unroll
        for (int k = 0; k < 16; k++) {
            float4 a0 = *(const float4*)&As[k][tr * 8];
            float4 a1 = *(const float4*)&As[k][tr * 8 + 4];
            ulonglong2 rb0 = *(const ulonglong2*)&Bs[k][tc * 8];
            ulonglong2 rb1 = *(const ulonglong2*)&Bs[k][tc * 8 + 4];
            float avv[8] = {a0.x, a0.y, a0.z, a0.w, a1.x, a1.y, a1.z, a1.w};
#pragma unroll
            for (int i = 0; i < 8; i++) {
                unsigned long long ra;
                PACK2(ra, avv[i]);
                FMA2(acc[i][0], ra, rb0.x, acc[i][0]);
                FMA2(acc[i][1], ra, rb0.y, acc[i][1]);
                FMA2(acc[i][2], ra, rb1.x, acc[i][2]);
                FMA2(acc[i][3], ra, rb1.y, acc[i][3]);
            }
        }
        __syncthreads();
    }

    float4 as0 = *(const float4*)&a_src[tc * 8];
    float4 as1 = *(const float4*)&a_src[tc * 8 + 4];
    float4 ad0 = *(const float4*)&a_dst[tc * 8];
    float4 ad1 = *(const float4*)&a_dst[tc * 8 + 4];

#pragma unroll
    for (int i = 0; i < 8; i++) {
        float c0, c1, c2, c3, c4, c5, c6, c7;
        UNPACK2(c0, c1, acc[i][0]);
        UNPACK2(c2, c3, acc[i][1]);
        UNPACK2(c4, c5, acc[i][2]);
        UNPACK2(c6, c7, acc[i][3]);

        int row = row0 + tr * 8 + i;
        if (row < M) {
            __half2 p01 = __floats2half2_rn(c0, c1);
            __half2 p23 = __floats2half2_rn(c2, c3);
            __half2 p45 = __floats2half2_rn(c4, c5);
            __half2 p67 = __floats2half2_rn(c6, c7);
            uint4 pk;
            pk.x = *(unsigned*)&p01; pk.y = *(unsigned*)&p23;
            pk.z = *(unsigned*)&p45; pk.w = *(unsigned*)&p67;
            *(uint4*)&C16[(size_t)row * 128 + tc * 8] = pk;
        }

        float ds = c0 * as0.x + c1 * as0.y + c2 * as0.z + c3 * as0.w
                 + c4 * as1.x + c5 * as1.y + c6 * as1.z + c7 * as1.w;
        float dd = c0 * ad0.x + c1 * ad0.y + c2 * ad0.z + c3 * ad0.w
                 + c4 * ad1.x + c5 * ad1.y + c6 * ad1.z + c7 * ad1.w;
#pragma unroll
        for (int o = 4; o > 0; o >>= 1) {
            ds += __shfl_down_sync(0xffffffffu, ds, o, 8);
            dd += __shfl_down_sync(0xffffffffu, dd, o, 8);
        }
        if (row < M && (tc & 7) == 0) {
            int head = tc >> 3;
            g_esrc[row * 2 + head] = ds;
            g_edst[row * 2 + head] = dd;
        }
    }
}

// ---------------- edge aggregation: one warp per dst ------------------------
// esrc loaded as float2 (both heads) at 8 deduplicated addresses per batch:
// all four lane-octets request the same 8 lines -> 8 wavefronts instead of 16.
__global__ __launch_bounds__(256) void k_agg(const float* __restrict__ bias,
                                             float* __restrict__ out, int do_relu) {
    int warp = (blockIdx.x * blockDim.x + threadIdx.x) >> 5;
    int lane = threadIdx.x & 31;
    if (warp >= N_NODES) return;

    const int d    = warp;
    const int head = lane >> 4;
    const float ed = __ldg(&g_edst[d * 2 + head]);
    const int beg  = __ldg(&g_rowptr[d]);
    const int end  = __ldg(&g_rowptr[d + 1]);

    const uint2* __restrict__ h2 = (const uint2*)g_h16;
    const int* __restrict__ col = g_col;
    const float2* __restrict__ esrc2 = (const float2*)g_esrc;

    float s = 0.f;
    float4 acc = make_float4(0.f, 0.f, 0.f, 0.f);

    int e = beg;
    // peel to 4-alignment (and short rows)
#pragma unroll 1
    for (; e < end && ((e & 3) || (end - e < 8)); e++) {
        int c0 = __ldg(&col[e]);
        float2 es2 = __ldg(&esrc2[c0]);               // 1 line, both heads
        float es0 = head ? es2.y : es2.x;
        uint2 r0 = __ldg(&h2[(size_t)c0 * 32 + lane]);
        float x0 = es0 + ed;
        float lv0 = fminf(x0 > 0.f ? x0 : NEG_SLOPE * x0, 80.f);
        float p0 = __expf(lv0);
        float2 f0a = __half22float2(*(__half2*)&r0.x);
        float2 f0b = __half22float2(*(__half2*)&r0.y);
        s += p0;
        acc.x += p0 * f0a.x;
        acc.y += p0 * f0a.y;
        acc.z += p0 * f0b.x;
        acc.w += p0 * f0b.y;
    }

    // 8-wide main loop
#pragma unroll 1
    for (; e + 8 <= end; e += 8) {
        int4 ca = __ldg((const int4*)&col[e]);
        int4 cb = __ldg((const int4*)&col[e + 4]);
        int cs[8] = {ca.x, ca.y, ca.z, ca.w, cb.x, cb.y, cb.z, cb.w};

        // all lane-octets request the SAME 8 addresses (dedup to 8 lines)
        int myc = cs[lane & 7];
        float2 es2 = __ldg(&esrc2[myc]);
        float es = (lane >= 16) ? es2.y : es2.x;

        uint2 r[8];
#pragma unroll
        for (int j = 0; j < 8; j++)
            r[j] = __ldg(&h2[(size_t)cs[j] * 32 + lane]);

        float x  = es + ed;
        float lv = fminf(x > 0.f ? x : NEG_SLOPE * x, 80.f);
        float myp = __expf(lv);

#pragma unroll
        for (int j = 0; j < 8; j++) {
            float pj = __shfl_sync(0xffffffffu, myp, j, 16);
            float2 fa = __half22float2(*(__half2*)&r[j].x);
            float2 fb = __half22float2(*(__half2*)&r[j].y);
            s += pj;
            acc.x += pj * fa.x;
            acc.y += pj * fa.y;
            acc.z += pj * fb.x;
            acc.w += pj * fb.y;
        }
    }

    // tail
#pragma unroll 1
    for (; e < end; e++) {
        int c0 = __ldg(&col[e]);
        float2 es2 = __ldg(&esrc2[c0]);
        float es0 = head ? es2.y : es2.x;
        uint2 r0 = __ldg(&h2[(size_t)c0 * 32 + lane]);
        float x0 = es0 + ed;
        float lv0 = fminf(x0 > 0.f ? x0 : NEG_SLOPE * x0, 80.f);
        float p0 = __expf(lv0);
        float2 f0a = __half22float2(*(__half2*)&r0.x);
        float2 f0b = __half22float2(*(__half2*)&r0.y);
        s += p0;
        acc.x += p0 * f0a.x;
        acc.y += p0 * f0a.y;
        acc.z += p0 * f0b.x;
        acc.w += p0 * f0b.y;
    }

    float inv = 1.f / (s + 1e-16f);
    float4 bv = __ldg(&((const float4*)bias)[lane]);
    float4 o;
    o.x = acc.x * inv + bv.x;
    o.y = acc.y * inv + bv.y;
    o.z = acc.z * inv + bv.z;
    o.w = acc.w * inv + bv.w;
    if (do_relu) {
        o.x = fmaxf(o.x, 0.f); o.y = fmaxf(o.y, 0.f);
        o.z = fmaxf(o.z, 0.f); o.w = fmaxf(o.w, 0.f);
    }
    ((float4*)out)[(size_t)d * 32 + lane] = o;
}

// ---------------- host side ----------------
static void run_layer(const float* xin, const float* W, const float* a_src,
                      const float* a_dst, const float* b, __half* h16,
                      float* out_buf, int do_relu) {
    const int gemm_blocks = (N_NODES + 127) / 128;
    k_sgemm_fused<<<gemm_blocks, 256>>>(xin, W, h16, a_src, a_dst, N_NODES);
    const int warp_blocks = (N_NODES * 32 + 255) / 256;
    k_agg<<<warp_blocks, 256>>>(b, out_buf, do_relu);
}

extern "C" void kernel_launch(void* const* d_in, const int* in_sizes, int n_in,
                              void* d_out, int out_size) {
    const float* x      = (const float*)d_in[0];
    const void*  ei     = d_in[1];
    const float* W_in   = (const float*)d_in[2];
    const float* as_in  = (const float*)d_in[3];
    const float* ad_in  = (const float*)d_in[4];
    const float* b_in   = (const float*)d_in[5];
    const float* W_h    = (const float*)d_in[6];
    const float* as_h   = (const float*)d_in[7];
    const float* ad_h   = (const float*)d_in[8];
    const float* b_h    = (const float*)d_in[9];
    const float* W_out  = (const float*)d_in[10];
    const float* as_out = (const float*)d_in[11];
    const float* ad_out = (const float*)d_in[12];
    const float* b_out  = (const float*)d_in[13];
    float* out = (float*)d_out;

    __half* p_h16 = nullptr;
    float*  p_x   = nullptr;
    cudaGetSymbolAddress((void**)&p_h16, g_h16);
    cudaGetSymbolAddress((void**)&p_x, g_x);

    // ---- CSR build (deterministic, recomputed each replay) ----
    const int eb = (N_EDGES + 255) / 256;
    const int nb = (N_NODES + 255) / 256;
    k_init_detect<<<nb, 256>>>((const long long*)ei);
    k_convert_hist<<<eb, 256>>>(ei);
    k_scan1<<<SCAN_NBLK, SCAN_BLK>>>();
    k_scan3_selfloop<<<SCAN_NBLK, SCAN_BLK>>>();
    k_scatter<<<eb, 256>>>();

    // ---- 4 GAT layers ----
    run_layer(x,   W_in,            as_in,      ad_in,      b_in,      p_h16, p_x, 1);
    run_layer(p_x, W_h,             as_h,       ad_h,       b_h,       p_h16, p_x, 1);
    run_layer(p_x, W_h + 128 * 128, as_h + 128, ad_h + 128, b_h + 128, p_h16, p_x, 1);
    run_layer(p_x, W_out,           as_out,     ad_out,     b_out,     p_h16, out, 0);
}

// round 12
// speedup vs baseline: 1.4775x; 1.4775x over previous
#include <cuda_runtime.h>
#include <cuda_fp16.h>

// Problem constants
#define N_NODES 50000
#define N_EDGES 1600000
#define E_TOT   (N_EDGES + N_NODES)
#define FDIM    128
#define NHEAD   2
#define NEG_SLOPE 0.2f

#define SCAN_BLK 1024
#define SCAN_NBLK ((N_NODES + SCAN_BLK - 1) / SCAN_BLK)   // 49

// ---------------- device scratch ----------------
__device__ int g_is64;
__device__ int g_src[N_EDGES];
__device__ int g_dst[N_EDGES];
__device__ int g_counts[N_NODES];
__device__ int g_rowptr[N_NODES + 1];
__device__ int g_fill[N_NODES];
__device__ __align__(16) int g_col[E_TOT];
__device__ int g_partials[64];
__device__ __align__(16) __half g_h16[(size_t)N_NODES * FDIM];   // fp16 features
__device__ __align__(16) float  g_x[(size_t)N_NODES * FDIM];     // fp32 layer output
__device__ __align__(16) float  g_esrc[N_NODES * NHEAD];         // [n][2] -> float2
__device__ __align__(16) float  g_edst[N_NODES * NHEAD];

// ---------------- packed f32x2 helpers ----------------
#define FMA2(d, a, b, c) \
    asm("fma.rn.f32x2 %0, %1, %2, %3;" : "=l"(d) : "l"(a), "l"(b), "l"(c))
#define PACK2(d, x) \
    asm("mov.b64 %0, {%1, %1};" : "=l"(d) : "r"(__float_as_uint(x)))
#define UNPACK2(lo, hi, v) \
    do { unsigned _l, _h; \
         asm("mov.b64 {%0, %1}, %2;" : "=r"(_l), "=r"(_h) : "l"(v)); \
         lo = __uint_as_float(_l); hi = __uint_as_float(_h); } while (0)

// ---------------- CSR build ----------------
__global__ void k_init_detect(const long long* ei) {
    int i = blockIdx.x * blockDim.x + threadIdx.x;
    if (i < N_NODES) g_counts[i] = 1;   // self loop
    if (i == 0) {
        int ok = 1;
        for (int t = 0; t < 16; t++) {
            long long v = ei[t];
            if (v < 0 || v >= (long long)N_NODES) { ok = 0; break; }
        }
        g_is64 = ok;
    }
}

__global__ void k_convert_hist(const void* eiv) {
    int e = blockIdx.x * blockDim.x + threadIdx.x;
    if (e >= N_EDGES) return;
    int s, d;
    if (g_is64) {
        const long long* p = (const long long*)eiv;
        s = (int)p[e];
        d = (int)p[N_EDGES + e];
    } else {
        const int* p = (const int*)eiv;
        s = p[e];
        d = p[N_EDGES + e];
    }
    g_src[e] = s;
    g_dst[e] = d;
    atomicAdd(&g_counts[d], 1);
}

__global__ void k_scan1() {
    __shared__ int sh[SCAN_BLK];
    int i = blockIdx.x * SCAN_BLK + threadIdx.x;
    int v = (i < N_NODES) ? g_counts[i] : 0;
    sh[threadIdx.x] = v;
    __syncthreads();
    for (int o = 1; o < SCAN_BLK; o <<= 1) {
        int t = 0;
        if ((int)threadIdx.x >= o) t = sh[threadIdx.x - o];
        __syncthreads();
        sh[threadIdx.x] += t;
        __syncthreads();
    }
    if (i < N_NODES) g_rowptr[i] = sh[threadIdx.x] - v;   // block-local exclusive
    if (threadIdx.x == SCAN_BLK - 1) g_partials[blockIdx.x] = sh[SCAN_BLK - 1];
}

__global__ void k_scan3_selfloop() {
    __shared__ int sh[64];
    if (threadIdx.x < 64)
        sh[threadIdx.x] = ((int)threadIdx.x < SCAN_NBLK) ? g_partials[threadIdx.x] : 0;
    __syncthreads();
    for (int o = 1; o < 64; o <<= 1) {
        int t = 0;
        if (threadIdx.x < 64 && (int)threadIdx.x >= o) t = sh[threadIdx.x - o];
        __syncthreads();
        if (threadIdx.x < 64) sh[threadIdx.x] += t;
        __syncthreads();
    }
    int blockOff = (blockIdx.x == 0) ? 0 : sh[blockIdx.x - 1];
    int i = blockIdx.x * SCAN_BLK + threadIdx.x;
    if (i < N_NODES) {
        int rp = g_rowptr[i] + blockOff;
        g_rowptr[i] = rp;
        g_col[rp] = i;      // self loop in slot 0
        g_fill[i] = 1;
    }
    if (i == 0) g_rowptr[N_NODES] = E_TOT;
}

__global__ void k_scatter() {
    int e = blockIdx.x * blockDim.x + threadIdx.x;
    if (e >= N_EDGES) return;
    int d = g_dst[e];
    int pos = g_rowptr[d] + atomicAdd(&g_fill[d], 1);
    g_col[pos] = g_src[e];
}

// ---------------- SGEMM (f32x2, BK=8 — the known-good R8 version) ----------
__global__ __launch_bounds__(256, 2) void k_sgemm_fused(
    const float* __restrict__ A, const float* __restrict__ B,
    __half* __restrict__ C16,
    const float* __restrict__ a_src, const float* __restrict__ a_dst, int M) {
    __shared__ float As[8][128];   // transposed: As[k][m]
    __shared__ float Bs[8][128];

    const int tid  = threadIdx.x;
    const int row0 = blockIdx.x * 128;
    const int tr   = tid >> 4;
    const int tc   = tid & 15;

    const int laRow = tid >> 1;
    const int laCol = (tid & 1) * 4;
    const int lbRow = tid >> 5;
    const int lbCol = (tid & 31) * 4;

    unsigned long long acc[8][4];
#pragma unroll
    for (int i = 0; i < 8; i++)
#pragma unroll
        for (int p = 0; p < 4; p++) acc[i][p] = 0ull;

    for (int k0 = 0; k0 < 128; k0 += 8) {
        float4 av = make_float4(0.f, 0.f, 0.f, 0.f);
        int arow = row0 + laRow;
        if (arow < M) av = *(const float4*)&A[(size_t)arow * 128 + k0 + laCol];
        As[laCol + 0][laRow] = av.x;
        As[laCol + 1][laRow] = av.y;
        As[laCol + 2][laRow] = av.z;
        As[laCol + 3][laRow] = av.w;

        *(float4*)&Bs[lbRow][lbCol] = *(const float4*)&B[(k0 + lbRow) * 128 + lbCol];
        __syncthreads();

#pragma unroll
        for (int k = 0; k < 8; k++) {
            float4 a0 = *(const float4*)&As[k][tr * 8];
            float4 a1 = *(const float4*)&As[k][tr * 8 + 4];
            ulonglong2 rb0 = *(const ulonglong2*)&Bs[k][tc * 8];
            ulonglong2 rb1 = *(const ulonglong2*)&Bs[k][tc * 8 + 4];
            float avv[8] = {a0.x, a0.y, a0.z, a0.w, a1.x, a1.y, a1.z, a1.w};
#pragma unroll
            for (int i = 0; i < 8; i++) {
                unsigned long long ra;
                PACK2(ra, avv[i]);
                FMA2(acc[i][0], ra, rb0.x, acc[i][0]);
                FMA2(acc[i][1], ra, rb0.y, acc[i][1]);
                FMA2(acc[i][2], ra, rb1.x, acc[i][2]);
                FMA2(acc[i][3], ra, rb1.y, acc[i][3]);
            }
        }
        __syncthreads();
    }

    float4 as0 = *(const float4*)&a_src[tc * 8];
    float4 as1 = *(const float4*)&a_src[tc * 8 + 4];
    float4 ad0 = *(const float4*)&a_dst[tc * 8];
    float4 ad1 = *(const float4*)&a_dst[tc * 8 + 4];

#pragma unroll
    for (int i = 0; i < 8; i++) {
        float c0, c1, c2, c3, c4, c5, c6, c7;
        UNPACK2(c0, c1, acc[i][0]);
        UNPACK2(c2, c3, acc[i][1]);
        UNPACK2(c4, c5, acc[i][2]);
        UNPACK2(c6, c7, acc[i][3]);

        int row = row0 + tr * 8 + i;
        if (row < M) {
            __half2 p01 = __floats2half2_rn(c0, c1);
            __half2 p23 = __floats2half2_rn(c2, c3);
            __half2 p45 = __floats2half2_rn(c4, c5);
            __half2 p67 = __floats2half2_rn(c6, c7);
            uint4 pk;
            pk.x = *(unsigned*)&p01; pk.y = *(unsigned*)&p23;
            pk.z = *(unsigned*)&p45; pk.w = *(unsigned*)&p67;
            *(uint4*)&C16[(size_t)row * 128 + tc * 8] = pk;
        }

        float ds = c0 * as0.x + c1 * as0.y + c2 * as0.z + c3 * as0.w
                 + c4 * as1.x + c5 * as1.y + c6 * as1.z + c7 * as1.w;
        float dd = c0 * ad0.x + c1 * ad0.y + c2 * ad0.z + c3 * ad0.w
                 + c4 * ad1.x + c5 * ad1.y + c6 * ad1.z + c7 * ad1.w;
#pragma unroll
        for (int o = 4; o > 0; o >>= 1) {
            ds += __shfl_down_sync(0xffffffffu, ds, o, 8);
            dd += __shfl_down_sync(0xffffffffu, dd, o, 8);
        }
        if (row < M && (tc & 7) == 0) {
            int head = tc >> 3;
            g_esrc[row * 2 + head] = ds;
            g_edst[row * 2 + head] = dd;
        }
    }
}

// ---------------- edge aggregation: one warp per dst ------------------------
// esrc loaded as float2 (both heads) at 8 deduplicated addresses per batch.
__global__ __launch_bounds__(256) void k_agg(const float* __restrict__ bias,
                                             float* __restrict__ out, int do_relu) {
    int warp = (blockIdx.x * blockDim.x + threadIdx.x) >> 5;
    int lane = threadIdx.x & 31;
    if (warp >= N_NODES) return;

    const int d    = warp;
    const int head = lane >> 4;
    const float ed = __ldg(&g_edst[d * 2 + head]);
    const int beg  = __ldg(&g_rowptr[d]);
    const int end  = __ldg(&g_rowptr[d + 1]);

    const uint2* __restrict__ h2 = (const uint2*)g_h16;
    const int* __restrict__ col = g_col;
    const float2* __restrict__ esrc2 = (const float2*)g_esrc;

    float s = 0.f;
    float4 acc = make_float4(0.f, 0.f, 0.f, 0.f);

    int e = beg;
    // peel to 4-alignment (and short rows)
#pragma unroll 1
    for (; e < end && ((e & 3) || (end - e < 8)); e++) {
        int c0 = __ldg(&col[e]);
        float2 es2 = __ldg(&esrc2[c0]);               // 1 line, both heads
        float es0 = head ? es2.y : es2.x;
        uint2 r0 = __ldg(&h2[(size_t)c0 * 32 + lane]);
        float x0 = es0 + ed;
        float lv0 = fminf(x0 > 0.f ? x0 : NEG_SLOPE * x0, 80.f);
        float p0 = __expf(lv0);
        float2 f0a = __half22float2(*(__half2*)&r0.x);
        float2 f0b = __half22float2(*(__half2*)&r0.y);
        s += p0;
        acc.x += p0 * f0a.x;
        acc.y += p0 * f0a.y;
        acc.z += p0 * f0b.x;
        acc.w += p0 * f0b.y;
    }

    // 8-wide main loop
#pragma unroll 1
    for (; e + 8 <= end; e += 8) {
        int4 ca = __ldg((const int4*)&col[e]);
        int4 cb = __ldg((const int4*)&col[e + 4]);
        int cs[8] = {ca.x, ca.y, ca.z, ca.w, cb.x, cb.y, cb.z, cb.w};

        // all lane-octets request the SAME 8 addresses (dedup to <=8 lines)
        int myc = cs[lane & 7];
        float2 es2 = __ldg(&esrc2[myc]);
        float es = (lane >= 16) ? es2.y : es2.x;

        uint2 r[8];
#pragma unroll
        for (int j = 0; j < 8; j++)
            r[j] = __ldg(&h2[(size_t)cs[j] * 32 + lane]);

        float x  = es + ed;
        float lv = fminf(x > 0.f ? x : NEG_SLOPE * x, 80.f);
        float myp = __expf(lv);

#pragma unroll
        for (int j = 0; j < 8; j++) {
            float pj = __shfl_sync(0xffffffffu, myp, j, 16);
            float2 fa = __half22float2(*(__half2*)&r[j].x);
            float2 fb = __half22float2(*(__half2*)&r[j].y);
            s += pj;
            acc.x += pj * fa.x;
            acc.y += pj * fa.y;
            acc.z += pj * fb.x;
            acc.w += pj * fb.y;
        }
    }

    // tail
#pragma unroll 1
    for (; e < end; e++) {
        int c0 = __ldg(&col[e]);
        float2 es2 = __ldg(&esrc2[c0]);
        float es0 = head ? es2.y : es2.x;
        uint2 r0 = __ldg(&h2[(size_t)c0 * 32 + lane]);
        float x0 = es0 + ed;
        float lv0 = fminf(x0 > 0.f ? x0 : NEG_SLOPE * x0, 80.f);
        float p0 = __expf(lv0);
        float2 f0a = __half22float2(*(__half2*)&r0.x);
        float2 f0b = __half22float2(*(__half2*)&r0.y);
        s += p0;
        acc.x += p0 * f0a.x;
        acc.y += p0 * f0a.y;
        acc.z += p0 * f0b.x;
        acc.w += p0 * f0b.y;
    }

    float inv = 1.f / (s + 1e-16f);
    float4 bv = __ldg(&((const float4*)bias)[lane]);
    float4 o;
    o.x = acc.x * inv + bv.x;
    o.y = acc.y * inv + bv.y;
    o.z = acc.z * inv + bv.z;
    o.w = acc.w * inv + bv.w;
    if (do_relu) {
        o.x = fmaxf(o.x, 0.f); o.y = fmaxf(o.y, 0.f);
        o.z = fmaxf(o.z, 0.f); o.w = fmaxf(o.w, 0.f);
    }
    ((float4*)out)[(size_t)d * 32 + lane] = o;
}

// ---------------- host side ----------------
static void run_layer(const float* xin, const float* W, const float* a_src,
                      const float* a_dst, const float* b, __half* h16,
                      float* out_buf, int do_relu) {
    const int gemm_blocks = (N_NODES + 127) / 128;
    k_sgemm_fused<<<gemm_blocks, 256>>>(xin, W, h16, a_src, a_dst, N_NODES);
    const int warp_blocks = (N_NODES * 32 + 255) / 256;
    k_agg<<<warp_blocks, 256>>>(b, out_buf, do_relu);
}

extern "C" void kernel_launch(void* const* d_in, const int* in_sizes, int n_in,
                              void* d_out, int out_size) {
    const float* x      = (const float*)d_in[0];
    const void*  ei     = d_in[1];
    const float* W_in   = (const float*)d_in[2];
    const float* as_in  = (const float*)d_in[3];
    const float* ad_in  = (const float*)d_in[4];
    const float* b_in   = (const float*)d_in[5];
    const float* W_h    = (const float*)d_in[6];
    const float* as_h   = (const float*)d_in[7];
    const float* ad_h   = (const float*)d_in[8];
    const float* b_h    = (const float*)d_in[9];
    const float* W_out  = (const float*)d_in[10];
    const float* as_out = (const float*)d_in[11];
    const float* ad_out = (const float*)d_in[12];
    const float* b_out  = (const float*)d_in[13];
    float* out = (float*)d_out;

    __half* p_h16 = nullptr;
    float*  p_x   = nullptr;
    cudaGetSymbolAddress((void**)&p_h16, g_h16);
    cudaGetSymbolAddress((void**)&p_x, g_x);

    // ---- CSR build (deterministic, recomputed each replay) ----
    const int eb = (N_EDGES + 255) / 256;
    const int nb = (N_NODES + 255) / 256;
    k_init_detect<<<nb, 256>>>((const long long*)ei);
    k_convert_hist<<<eb, 256>>>(ei);
    k_scan1<<<SCAN_NBLK, SCAN_BLK>>>();
    k_scan3_selfloop<<<SCAN_NBLK, SCAN_BLK>>>();
    k_scatter<<<eb, 256>>>();

    // ---- 4 GAT layers ----
    run_layer(x,   W_in,            as_in,      ad_in,      b_in,      p_h16, p_x, 1);
    run_layer(p_x, W_h,             as_h,       ad_h,       b_h,       p_h16, p_x, 1);
    run_layer(p_x, W_h + 128 * 128, as_h + 128, ad_h + 128, b_h + 128, p_h16, p_x, 1);
    run_layer(p_x, W_out,           as_out,     ad_out,     b_out,     p_h16, out, 0);
}

// round 13
// speedup vs baseline: 1.5208x; 1.0293x over previous
#include <cuda_runtime.h>
#include <cuda_fp16.h>

// Problem constants
#define N_NODES 50000
#define N_EDGES 1600000
#define E_TOT   (N_EDGES + N_NODES)
#define FDIM    128
#define NHEAD   2
#define NEG_SLOPE 0.2f

#define SCAN_BLK 1024
#define SCAN_NBLK ((N_NODES + SCAN_BLK - 1) / SCAN_BLK)   // 49

// ---------------- device scratch ----------------
__device__ int g_is64;
__device__ int g_src[N_EDGES];
__device__ int g_dst[N_EDGES];
__device__ int g_counts[N_NODES];
__device__ int g_rowptr[N_NODES + 1];
__device__ int g_fill[N_NODES];
__device__ __align__(16) int g_col[E_TOT + 8];   // +8 pad for masked 8-wide tail
__device__ int g_partials[64];
__device__ __align__(16) __half g_h16[(size_t)N_NODES * FDIM];   // fp16 features
__device__ __align__(16) float  g_x[(size_t)N_NODES * FDIM];     // fp32 layer output
__device__ __align__(16) float  g_esrc[N_NODES * NHEAD];         // [n][2] -> float2
__device__ __align__(16) float  g_edst[N_NODES * NHEAD];

// ---------------- packed f32x2 helpers ----------------
#define FMA2(d, a, b, c) \
    asm("fma.rn.f32x2 %0, %1, %2, %3;" : "=l"(d) : "l"(a), "l"(b), "l"(c))
#define PACK2(d, x) \
    asm("mov.b64 %0, {%1, %1};" : "=l"(d) : "r"(__float_as_uint(x)))
#define UNPACK2(lo, hi, v) \
    do { unsigned _l, _h; \
         asm("mov.b64 {%0, %1}, %2;" : "=r"(_l), "=r"(_h) : "l"(v)); \
         lo = __uint_as_float(_l); hi = __uint_as_float(_h); } while (0)

// ---------------- CSR build ----------------
__global__ void k_init_detect(const long long* ei) {
    int i = blockIdx.x * blockDim.x + threadIdx.x;
    if (i < N_NODES) g_counts[i] = 1;   // self loop
    if (i == 0) {
        int ok = 1;
        for (int t = 0; t < 16; t++) {
            long long v = ei[t];
            if (v < 0 || v >= (long long)N_NODES) { ok = 0; break; }
        }
        g_is64 = ok;
    }
}

__global__ void k_convert_hist(const void* eiv) {
    int e = blockIdx.x * blockDim.x + threadIdx.x;
    if (e >= N_EDGES) return;
    int s, d;
    if (g_is64) {
        const long long* p = (const long long*)eiv;
        s = (int)p[e];
        d = (int)p[N_EDGES + e];
    } else {
        const int* p = (const int*)eiv;
        s = p[e];
        d = p[N_EDGES + e];
    }
    g_src[e] = s;
    g_dst[e] = d;
    atomicAdd(&g_counts[d], 1);
}

__global__ void k_scan1() {
    __shared__ int sh[SCAN_BLK];
    int i = blockIdx.x * SCAN_BLK + threadIdx.x;
    int v = (i < N_NODES) ? g_counts[i] : 0;
    sh[threadIdx.x] = v;
    __syncthreads();
    for (int o = 1; o < SCAN_BLK; o <<= 1) {
        int t = 0;
        if ((int)threadIdx.x >= o) t = sh[threadIdx.x - o];
        __syncthreads();
        sh[threadIdx.x] += t;
        __syncthreads();
    }
    if (i < N_NODES) g_rowptr[i] = sh[threadIdx.x] - v;   // block-local exclusive
    if (threadIdx.x == SCAN_BLK - 1) g_partials[blockIdx.x] = sh[SCAN_BLK - 1];
}

__global__ void k_scan3_selfloop() {
    __shared__ int sh[64];
    if (threadIdx.x < 64)
        sh[threadIdx.x] = ((int)threadIdx.x < SCAN_NBLK) ? g_partials[threadIdx.x] : 0;
    __syncthreads();
    for (int o = 1; o < 64; o <<= 1) {
        int t = 0;
        if (threadIdx.x < 64 && (int)threadIdx.x >= o) t = sh[threadIdx.x - o];
        __syncthreads();
        if (threadIdx.x < 64) sh[threadIdx.x] += t;
        __syncthreads();
    }
    int blockOff = (blockIdx.x == 0) ? 0 : sh[blockIdx.x - 1];
    int i = blockIdx.x * SCAN_BLK + threadIdx.x;
    if (i < N_NODES) {
        int rp = g_rowptr[i] + blockOff;
        g_rowptr[i] = rp;
        g_col[rp] = i;      // self loop in slot 0
        g_fill[i] = 1;
    }
    if (i == 0) g_rowptr[N_NODES] = E_TOT;
}

__global__ void k_scatter() {
    int e = blockIdx.x * blockDim.x + threadIdx.x;
    if (e >= N_EDGES) return;
    int d = g_dst[e];
    int pos = g_rowptr[d] + atomicAdd(&g_fill[d], 1);
    g_col[pos] = g_src[e];
}

// ---------------- SGEMM (f32x2, BK=8 — known-good) + fused logits ----------
__global__ __launch_bounds__(256, 2) void k_sgemm_fused(
    const float* __restrict__ A, const float* __restrict__ B,
    __half* __restrict__ C16,
    const float* __restrict__ a_src, const float* __restrict__ a_dst, int M) {
    __shared__ float As[8][128];   // transposed: As[k][m]
    __shared__ float Bs[8][128];

    const int tid  = threadIdx.x;
    const int row0 = blockIdx.x * 128;
    const int tr   = tid >> 4;
    const int tc   = tid & 15;

    const int laRow = tid >> 1;
    const int laCol = (tid & 1) * 4;
    const int lbRow = tid >> 5;
    const int lbCol = (tid & 31) * 4;

    unsigned long long acc[8][4];
#pragma unroll
    for (int i = 0; i < 8; i++)
#pragma unroll
        for (int p = 0; p < 4; p++) acc[i][p] = 0ull;

    for (int k0 = 0; k0 < 128; k0 += 8) {
        float4 av = make_float4(0.f, 0.f, 0.f, 0.f);
        int arow = row0 + laRow;
        if (arow < M) av = *(const float4*)&A[(size_t)arow * 128 + k0 + laCol];
        As[laCol + 0][laRow] = av.x;
        As[laCol + 1][laRow] = av.y;
        As[laCol + 2][laRow] = av.z;
        As[laCol + 3][laRow] = av.w;

        *(float4*)&Bs[lbRow][lbCol] = *(const float4*)&B[(k0 + lbRow) * 128 + lbCol];
        __syncthreads();

#pragma unroll
        for (int k = 0; k < 8; k++) {
            float4 a0 = *(const float4*)&As[k][tr * 8];
            float4 a1 = *(const float4*)&As[k][tr * 8 + 4];
            ulonglong2 rb0 = *(const ulonglong2*)&Bs[k][tc * 8];
            ulonglong2 rb1 = *(const ulonglong2*)&Bs[k][tc * 8 + 4];
            float avv[8] = {a0.x, a0.y, a0.z, a0.w, a1.x, a1.y, a1.z, a1.w};
#pragma unroll
            for (int i = 0; i < 8; i++) {
                unsigned long long ra;
                PACK2(ra, avv[i]);
                FMA2(acc[i][0], ra, rb0.x, acc[i][0]);
                FMA2(acc[i][1], ra, rb0.y, acc[i][1]);
                FMA2(acc[i][2], ra, rb1.x, acc[i][2]);
                FMA2(acc[i][3], ra, rb1.y, acc[i][3]);
            }
        }
        __syncthreads();
    }

    float4 as0 = *(const float4*)&a_src[tc * 8];
    float4 as1 = *(const float4*)&a_src[tc * 8 + 4];
    float4 ad0 = *(const float4*)&a_dst[tc * 8];
    float4 ad1 = *(const float4*)&a_dst[tc * 8 + 4];

#pragma unroll
    for (int i = 0; i < 8; i++) {
        float c0, c1, c2, c3, c4, c5, c6, c7;
        UNPACK2(c0, c1, acc[i][0]);
        UNPACK2(c2, c3, acc[i][1]);
        UNPACK2(c4, c5, acc[i][2]);
        UNPACK2(c6, c7, acc[i][3]);

        int row = row0 + tr * 8 + i;
        if (row < M) {
            __half2 p01 = __floats2half2_rn(c0, c1);
            __half2 p23 = __floats2half2_rn(c2, c3);
            __half2 p45 = __floats2half2_rn(c4, c5);
            __half2 p67 = __floats2half2_rn(c6, c7);
            uint4 pk;
            pk.x = *(unsigned*)&p01; pk.y = *(unsigned*)&p23;
            pk.z = *(unsigned*)&p45; pk.w = *(unsigned*)&p67;
            *(uint4*)&C16[(size_t)row * 128 + tc * 8] = pk;
        }

        float ds = c0 * as0.x + c1 * as0.y + c2 * as0.z + c3 * as0.w
                 + c4 * as1.x + c5 * as1.y + c6 * as1.z + c7 * as1.w;
        float dd = c0 * ad0.x + c1 * ad0.y + c2 * ad0.z + c3 * ad0.w
                 + c4 * ad1.x + c5 * ad1.y + c6 * ad1.z + c7 * ad1.w;
#pragma unroll
        for (int o = 4; o > 0; o >>= 1) {
            ds += __shfl_down_sync(0xffffffffu, ds, o, 8);
            dd += __shfl_down_sync(0xffffffffu, dd, o, 8);
        }
        if (row < M && (tc & 7) == 0) {
            int head = tc >> 3;
            g_esrc[row * 2 + head] = ds;
            g_edst[row * 2 + head] = dd;
        }
    }
}

// ---------------- edge aggregation: one warp per dst ------------------------
__global__ __launch_bounds__(256) void k_agg(const float* __restrict__ bias,
                                             float* __restrict__ out, int do_relu) {
    int warp = (blockIdx.x * blockDim.x + threadIdx.x) >> 5;
    int lane = threadIdx.x & 31;
    if (warp >= N_NODES) return;

    const int d    = warp;
    const int head = lane >> 4;
    const float ed = __ldg(&g_edst[d * 2 + head]);
    const int beg  = __ldg(&g_rowptr[d]);
    const int end  = __ldg(&g_rowptr[d + 1]);

    const uint2* __restrict__ h2 = (const uint2*)g_h16;
    const int* __restrict__ col = g_col;
    const float2* __restrict__ esrc2 = (const float2*)g_esrc;

    float s = 0.f;
    float4 acc = make_float4(0.f, 0.f, 0.f, 0.f);

    int e = beg;
    // peel to int4 alignment only (<=3 iterations)
#pragma unroll 1
    for (; e < end && (e & 3); e++) {
        int c0 = __ldg(&col[e]);
        float2 es2 = __ldg(&esrc2[c0]);
        float es0 = head ? es2.y : es2.x;
        uint2 r0 = __ldg(&h2[(size_t)c0 * 32 + lane]);
        float x0 = es0 + ed;
        float lv0 = fminf(x0 > 0.f ? x0 : NEG_SLOPE * x0, 80.f);
        float p0 = __expf(lv0);
        float2 f0a = __half22float2(*(__half2*)&r0.x);
        float2 f0b = __half22float2(*(__half2*)&r0.y);
        s += p0;
        acc.x += p0 * f0a.x;
        acc.y += p0 * f0a.y;
        acc.z += p0 * f0b.x;
        acc.w += p0 * f0b.y;
    }

    // 8-wide main loop
#pragma unroll 1
    for (; e + 8 <= end; e += 8) {
        int4 ca = __ldg((const int4*)&col[e]);
        int4 cb = __ldg((const int4*)&col[e + 4]);
        int cs[8] = {ca.x, ca.y, ca.z, ca.w, cb.x, cb.y, cb.z, cb.w};

        int myc = cs[lane & 7];
        float2 es2 = __ldg(&esrc2[myc]);
        float es = (lane >= 16) ? es2.y : es2.x;

        uint2 r[8];
#pragma unroll
        for (int j = 0; j < 8; j++)
            r[j] = __ldg(&h2[(size_t)cs[j] * 32 + lane]);

        float x  = es + ed;
        float lv = fminf(x > 0.f ? x : NEG_SLOPE * x, 80.f);
        float myp = __expf(lv);

#pragma unroll
        for (int j = 0; j < 8; j++) {
            float pj = __shfl_sync(0xffffffffu, myp, j, 16);
            float2 fa = __half22float2(*(__half2*)&r[j].x);
            float2 fb = __half22float2(*(__half2*)&r[j].y);
            s += pj;
            acc.x += pj * fa.x;
            acc.y += pj * fa.y;
            acc.z += pj * fb.x;
            acc.w += pj * fb.y;
        }
    }

    // masked 8-wide tail (e is 4-aligned here; g_col padded by 8)
    if (e < end) {
        int rem = end - e;                       // 1..7
        int4 ca = __ldg((const int4*)&col[e]);
        int4 cb = __ldg((const int4*)&col[e + 4]);
        int cs[8] = {ca.x, ca.y, ca.z, ca.w, cb.x, cb.y, cb.z, cb.w};
        int c0v = cs[0];
#pragma unroll
        for (int j = 0; j < 8; j++) cs[j] = (j < rem) ? cs[j] : c0v;

        int myc = cs[lane & 7];
        float2 es2 = __ldg(&esrc2[myc]);
        float es = (lane >= 16) ? es2.y : es2.x;

        uint2 r[8];
#pragma unroll
        for (int j = 0; j < 8; j++)
            r[j] = __ldg(&h2[(size_t)cs[j] * 32 + lane]);

        float x  = es + ed;
        float lv = fminf(x > 0.f ? x : NEG_SLOPE * x, 80.f);
        float myp = ((lane & 7) < rem) ? __expf(lv) : 0.f;

#pragma unroll
        for (int j = 0; j < 8; j++) {
            float pj = __shfl_sync(0xffffffffu, myp, j, 16);
            float2 fa = __half22float2(*(__half2*)&r[j].x);
            float2 fb = __half22float2(*(__half2*)&r[j].y);
            s += pj;
            acc.x += pj * fa.x;
            acc.y += pj * fa.y;
            acc.z += pj * fb.x;
            acc.w += pj * fb.y;
        }
    }

    float inv = 1.f / (s + 1e-16f);
    float4 bv = __ldg(&((const float4*)bias)[lane]);
    float4 o;
    o.x = acc.x * inv + bv.x;
    o.y = acc.y * inv + bv.y;
    o.z = acc.z * inv + bv.z;
    o.w = acc.w * inv + bv.w;
    if (do_relu) {
        o.x = fmaxf(o.x, 0.f); o.y = fmaxf(o.y, 0.f);
        o.z = fmaxf(o.z, 0.f); o.w = fmaxf(o.w, 0.f);
    }
    ((float4*)out)[(size_t)d * 32 + lane] = o;
}

// ---------------- host side ----------------
static cudaStream_t s_csr = nullptr;
static cudaEvent_t  ev_fork = nullptr, ev_join = nullptr;

extern "C" void kernel_launch(void* const* d_in, const int* in_sizes, int n_in,
                              void* d_out, int out_size) {
    const float* x      = (const float*)d_in[0];
    const void*  ei     = d_in[1];
    const float* W_in   = (const float*)d_in[2];
    const float* as_in  = (const float*)d_in[3];
    const float* ad_in  = (const float*)d_in[4];
    const float* b_in   = (const float*)d_in[5];
    const float* W_h    = (const float*)d_in[6];
    const float* as_h   = (const float*)d_in[7];
    const float* ad_h   = (const float*)d_in[8];
    const float* b_h    = (const float*)d_in[9];
    const float* W_out  = (const float*)d_in[10];
    const float* as_out = (const float*)d_in[11];
    const float* ad_out = (const float*)d_in[12];
    const float* b_out  = (const float*)d_in[13];
    float* out = (float*)d_out;

    __half* p_h16 = nullptr;
    float*  p_x   = nullptr;
    cudaGetSymbolAddress((void**)&p_h16, g_h16);
    cudaGetSymbolAddress((void**)&p_x, g_x);

    // lazy init (first call is the uncaptured correctness run)
    if (!s_csr) {
        cudaStreamCreate(&s_csr);
        cudaEventCreateWithFlags(&ev_fork, cudaEventDisableTiming);
        cudaEventCreateWithFlags(&ev_join, cudaEventDisableTiming);
    }

    const int eb = (N_EDGES + 255) / 256;
    const int nb = (N_NODES + 255) / 256;
    const int gemm_blocks = (N_NODES + 127) / 128;
    const int warp_blocks = (N_NODES * 32 + 255) / 256;

    // ---- fork: CSR build on side stream, layer-0 GEMM in parallel ----
    cudaEventRecord(ev_fork, 0);
    cudaStreamWaitEvent(s_csr, ev_fork, 0);
    k_init_detect<<<nb, 256, 0, s_csr>>>((const long long*)ei);
    k_convert_hist<<<eb, 256, 0, s_csr>>>(ei);
    k_scan1<<<SCAN_NBLK, SCAN_BLK, 0, s_csr>>>();
    k_scan3_selfloop<<<SCAN_NBLK, SCAN_BLK, 0, s_csr>>>();
    k_scatter<<<eb, 256, 0, s_csr>>>();
    cudaEventRecord(ev_join, s_csr);

    k_sgemm_fused<<<gemm_blocks, 256>>>(x, W_in, p_h16, as_in, ad_in, N_NODES);

    // ---- join: agg layer 0 needs the CSR ----
    cudaStreamWaitEvent(0, ev_join, 0);
    k_agg<<<warp_blocks, 256>>>(b_in, p_x, 1);

    // ---- layers 1..3 serial ----
    k_sgemm_fused<<<gemm_blocks, 256>>>(p_x, W_h, p_h16, as_h, ad_h, N_NODES);
    k_agg<<<warp_blocks, 256>>>(b_h, p_x, 1);

    k_sgemm_fused<<<gemm_blocks, 256>>>(p_x, W_h + 128 * 128, p_h16,
                                        as_h + 128, ad_h + 128, N_NODES);
    k_agg<<<warp_blocks, 256>>>(b_h + 128, p_x, 1);

    k_sgemm_fused<<<gemm_blocks, 256>>>(p_x, W_out, p_h16, as_out, ad_out, N_NODES);
    k_agg<<<warp_blocks, 256>>>(b_out, out, 0);
}

// round 14
// speedup vs baseline: 2.1931x; 1.4421x over previous
#include <cuda_runtime.h>
#include <cuda_fp16.h>
#include <mma.h>

using namespace nvcuda;

// Problem constants
#define N_NODES 50000
#define N_EDGES 1600000
#define E_TOT   (N_EDGES + N_NODES)
#define FDIM    128
#define NHEAD   2
#define NEG_SLOPE 0.2f

#define SCAN_BLK 1024
#define SCAN_NBLK ((N_NODES + SCAN_BLK - 1) / SCAN_BLK)   // 49

#define LDA 136   // halves; 272B row stride (16B multiple, LDSM conflict-free)
#define LDC 132   // floats; 528B row stride (16B multiple)
#define GEMM_SMEM (2 * 128 * LDA * (int)sizeof(__half))   // 69632 B

// ---------------- device scratch ----------------
__device__ int g_is64;
__device__ int g_src[N_EDGES];
__device__ int g_dst[N_EDGES];
__device__ int g_counts[N_NODES];
__device__ int g_rowptr[N_NODES + 1];
__device__ int g_fill[N_NODES];
__device__ __align__(16) int g_col[E_TOT + 8];   // +8 pad for masked tail
__device__ int g_partials[64];
__device__ __align__(16) __half g_h16[(size_t)N_NODES * FDIM];
__device__ __align__(16) float  g_x[(size_t)N_NODES * FDIM];
__device__ __align__(16) float  g_esrc[N_NODES * NHEAD];   // [n][2] -> float2
__device__ __align__(16) float  g_edst[N_NODES * NHEAD];

// ---------------- CSR build ----------------
__global__ void k_init_detect(const long long* ei) {
    int i = blockIdx.x * blockDim.x + threadIdx.x;
    if (i < N_NODES) g_counts[i] = 1;   // self loop
    if (i == 0) {
        int ok = 1;
        for (int t = 0; t < 16; t++) {
            long long v = ei[t];
            if (v < 0 || v >= (long long)N_NODES) { ok = 0; break; }
        }
        g_is64 = ok;
    }
}

__global__ void k_convert_hist(const void* eiv) {
    int e = blockIdx.x * blockDim.x + threadIdx.x;
    if (e >= N_EDGES) return;
    int s, d;
    if (g_is64) {
        const long long* p = (const long long*)eiv;
        s = (int)p[e];
        d = (int)p[N_EDGES + e];
    } else {
        const int* p = (const int*)eiv;
        s = p[e];
        d = p[N_EDGES + e];
    }
    g_src[e] = s;
    g_dst[e] = d;
    atomicAdd(&g_counts[d], 1);
}

__global__ void k_scan1() {
    __shared__ int sh[SCAN_BLK];
    int i = blockIdx.x * SCAN_BLK + threadIdx.x;
    int v = (i < N_NODES) ? g_counts[i] : 0;
    sh[threadIdx.x] = v;
    __syncthreads();
    for (int o = 1; o < SCAN_BLK; o <<= 1) {
        int t = 0;
        if ((int)threadIdx.x >= o) t = sh[threadIdx.x - o];
        __syncthreads();
        sh[threadIdx.x] += t;
        __syncthreads();
    }
    if (i < N_NODES) g_rowptr[i] = sh[threadIdx.x] - v;
    if (threadIdx.x == SCAN_BLK - 1) g_partials[blockIdx.x] = sh[SCAN_BLK - 1];
}

__global__ void k_scan3_selfloop() {
    __shared__ int sh[64];
    if (threadIdx.x < 64)
        sh[threadIdx.x] = ((int)threadIdx.x < SCAN_NBLK) ? g_partials[threadIdx.x] : 0;
    __syncthreads();
    for (int o = 1; o < 64; o <<= 1) {
        int t = 0;
        if (threadIdx.x < 64 && (int)threadIdx.x >= o) t = sh[threadIdx.x - o];
        __syncthreads();
        if (threadIdx.x < 64) sh[threadIdx.x] += t;
        __syncthreads();
    }
    int blockOff = (blockIdx.x == 0) ? 0 : sh[blockIdx.x - 1];
    int i = blockIdx.x * SCAN_BLK + threadIdx.x;
    if (i < N_NODES) {
        int rp = g_rowptr[i] + blockOff;
        g_rowptr[i] = rp;
        g_col[rp] = i;      // self loop in slot 0
        g_fill[i] = 1;
    }
    if (i == 0) g_rowptr[N_NODES] = E_TOT;
}

__global__ void k_scatter() {
    int e = blockIdx.x * blockDim.x + threadIdx.x;
    if (e >= N_EDGES) return;
    int d = g_dst[e];
    int pos = g_rowptr[d] + atomicAdd(&g_fill[d], 1);
    g_col[pos] = g_src[e];
}

// ---------------- HMMA GEMM (wmma fp16 x fp16 -> fp32) + fused logits -------
// C[128,128] tile per CTA; A,W converted fp32->fp16 into smem; full K staged.
extern __shared__ char dynsmem[];

__global__ void k_gemm_wmma_fused(
    const float* __restrict__ A, const float* __restrict__ B,
    __half* __restrict__ C16,
    const float* __restrict__ a_src, const float* __restrict__ a_dst, int M) {
    __half* As = (__half*)dynsmem;          // 128 x LDA
    __half* Bs = As + 128 * LDA;            // 128 x LDA
    float*  Cs = (float*)dynsmem;           // reused for epilogue, 128 x LDC

    const int tid  = threadIdx.x;
    const int wid  = tid >> 5;
    const int row0 = blockIdx.x * 128;

    // ---- stage A (guarded) and B(=W) as fp16 ----
#pragma unroll
    for (int i = 0; i < 16; i++) {
        int lin = tid + i * 256;          // float4 index in 128x128
        int row = lin >> 5;               // 32 float4 per row
        int col = (lin & 31) * 4;

        float4 v = make_float4(0.f, 0.f, 0.f, 0.f);
        if (row0 + row < M) v = *(const float4*)&A[(size_t)(row0 + row) * 128 + col];
        __half2 a01 = __floats2half2_rn(v.x, v.y);
        __half2 a23 = __floats2half2_rn(v.z, v.w);
        uint2 pa;
        pa.x = *(unsigned*)&a01; pa.y = *(unsigned*)&a23;
        *(uint2*)&As[row * LDA + col] = pa;

        float4 w = *(const float4*)&B[lin * 4];   // B[row*128+col] contiguous
        __half2 b01 = __floats2half2_rn(w.x, w.y);
        __half2 b23 = __floats2half2_rn(w.z, w.w);
        uint2 pb;
        pb.x = *(unsigned*)&b01; pb.y = *(unsigned*)&b23;
        *(uint2*)&Bs[row * LDA + col] = pb;
    }
    __syncthreads();

    // ---- mma: warp (wm 0..3, wn 0..1) computes 32x64 ----
    const int wm = wid & 3;
    const int wn = wid >> 2;

    wmma::fragment<wmma::accumulator, 16, 16, 16, float> acc[2][4];
#pragma unroll
    for (int a = 0; a < 2; a++)
#pragma unroll
        for (int b = 0; b < 4; b++) wmma::fill_fragment(acc[a][b], 0.f);

#pragma unroll
    for (int kk = 0; kk < 128; kk += 16) {
        wmma::fragment<wmma::matrix_a, 16, 16, 16, __half, wmma::row_major> af[2];
        wmma::fragment<wmma::matrix_b, 16, 16, 16, __half, wmma::row_major> bf[4];
#pragma unroll
        for (int a = 0; a < 2; a++)
            wmma::load_matrix_sync(af[a], &As[(wm * 32 + a * 16) * LDA + kk], LDA);
#pragma unroll
        for (int b = 0; b < 4; b++)
            wmma::load_matrix_sync(bf[b], &Bs[kk * LDA + wn * 64 + b * 16], LDA);
#pragma unroll
        for (int a = 0; a < 2; a++)
#pragma unroll
            for (int b = 0; b < 4; b++)
                wmma::mma_sync(acc[a][b], af[a], bf[b], acc[a][b]);
    }
    __syncthreads();   // done reading As/Bs; reuse as Cs

#pragma unroll
    for (int a = 0; a < 2; a++)
#pragma unroll
        for (int b = 0; b < 4; b++)
            wmma::store_matrix_sync(&Cs[(wm * 32 + a * 16) * LDC + wn * 64 + b * 16],
                                    acc[a][b], LDC, wmma::mem_row_major);
    __syncthreads();

    // ---- epilogue: fp16 store + fused logit dots (reads Cs) ----
    const int tr = tid >> 4;
    const int tc = tid & 15;

    float4 as0 = *(const float4*)&a_src[tc * 8];
    float4 as1 = *(const float4*)&a_src[tc * 8 + 4];
    float4 ad0 = *(const float4*)&a_dst[tc * 8];
    float4 ad1 = *(const float4*)&a_dst[tc * 8 + 4];

#pragma unroll
    for (int i = 0; i < 8; i++) {
        int srow = tr * 8 + i;
        float4 cA = *(const float4*)&Cs[srow * LDC + tc * 8];
        float4 cB = *(const float4*)&Cs[srow * LDC + tc * 8 + 4];
        float c0 = cA.x, c1 = cA.y, c2 = cA.z, c3 = cA.w;
        float c4 = cB.x, c5 = cB.y, c6 = cB.z, c7 = cB.w;

        int row = row0 + srow;
        if (row < M) {
            __half2 p01 = __floats2half2_rn(c0, c1);
            __half2 p23 = __floats2half2_rn(c2, c3);
            __half2 p45 = __floats2half2_rn(c4, c5);
            __half2 p67 = __floats2half2_rn(c6, c7);
            uint4 pk;
            pk.x = *(unsigned*)&p01; pk.y = *(unsigned*)&p23;
            pk.z = *(unsigned*)&p45; pk.w = *(unsigned*)&p67;
            *(uint4*)&C16[(size_t)row * 128 + tc * 8] = pk;
        }

        float ds = c0 * as0.x + c1 * as0.y + c2 * as0.z + c3 * as0.w
                 + c4 * as1.x + c5 * as1.y + c6 * as1.z + c7 * as1.w;
        float dd = c0 * ad0.x + c1 * ad0.y + c2 * ad0.z + c3 * ad0.w
                 + c4 * ad1.x + c5 * ad1.y + c6 * ad1.z + c7 * ad1.w;
#pragma unroll
        for (int o = 4; o > 0; o >>= 1) {
            ds += __shfl_down_sync(0xffffffffu, ds, o, 8);
            dd += __shfl_down_sync(0xffffffffu, dd, o, 8);
        }
        if (row < M && (tc & 7) == 0) {
            int head = tc >> 3;
            g_esrc[row * 2 + head] = ds;
            g_edst[row * 2 + head] = dd;
        }
    }
}

// ---------------- edge aggregation: one warp per dst ------------------------
__global__ __launch_bounds__(256) void k_agg(const float* __restrict__ bias,
                                             float* __restrict__ out, int do_relu) {
    int warp = (blockIdx.x * blockDim.x + threadIdx.x) >> 5;
    int lane = threadIdx.x & 31;
    if (warp >= N_NODES) return;

    const int d    = warp;
    const int head = lane >> 4;
    const float ed = __ldg(&g_edst[d * 2 + head]);
    const int beg  = __ldg(&g_rowptr[d]);
    const int end  = __ldg(&g_rowptr[d + 1]);

    const uint2* __restrict__ h2 = (const uint2*)g_h16;
    const int* __restrict__ col = g_col;
    const float2* __restrict__ esrc2 = (const float2*)g_esrc;

    float s = 0.f;
    float4 acc = make_float4(0.f, 0.f, 0.f, 0.f);

    int e = beg;
#pragma unroll 1
    for (; e < end && (e & 3); e++) {
        int c0 = __ldg(&col[e]);
        float2 es2 = __ldg(&esrc2[c0]);
        float es0 = head ? es2.y : es2.x;
        uint2 r0 = __ldg(&h2[(size_t)c0 * 32 + lane]);
        float x0 = es0 + ed;
        float lv0 = fminf(x0 > 0.f ? x0 : NEG_SLOPE * x0, 80.f);
        float p0 = __expf(lv0);
        float2 f0a = __half22float2(*(__half2*)&r0.x);
        float2 f0b = __half22float2(*(__half2*)&r0.y);
        s += p0;
        acc.x += p0 * f0a.x;
        acc.y += p0 * f0a.y;
        acc.z += p0 * f0b.x;
        acc.w += p0 * f0b.y;
    }

#pragma unroll 1
    for (; e + 8 <= end; e += 8) {
        int4 ca = __ldg((const int4*)&col[e]);
        int4 cb = __ldg((const int4*)&col[e + 4]);
        int cs[8] = {ca.x, ca.y, ca.z, ca.w, cb.x, cb.y, cb.z, cb.w};

        int myc = cs[lane & 7];
        float2 es2 = __ldg(&esrc2[myc]);
        float es = (lane >= 16) ? es2.y : es2.x;

        uint2 r[8];
#pragma unroll
        for (int j = 0; j < 8; j++)
            r[j] = __ldg(&h2[(size_t)cs[j] * 32 + lane]);

        float x  = es + ed;
        float lv = fminf(x > 0.f ? x : NEG_SLOPE * x, 80.f);
        float myp = __expf(lv);

#pragma unroll
        for (int j = 0; j < 8; j++) {
            float pj = __shfl_sync(0xffffffffu, myp, j, 16);
            float2 fa = __half22float2(*(__half2*)&r[j].x);
            float2 fb = __half22float2(*(__half2*)&r[j].y);
            s += pj;
            acc.x += pj * fa.x;
            acc.y += pj * fa.y;
            acc.z += pj * fb.x;
            acc.w += pj * fb.y;
        }
    }

    if (e < end) {
        int rem = end - e;
        int4 ca = __ldg((const int4*)&col[e]);
        int4 cb = __ldg((const int4*)&col[e + 4]);
        int cs[8] = {ca.x, ca.y, ca.z, ca.w, cb.x, cb.y, cb.z, cb.w};
        int c0v = cs[0];
#pragma unroll
        for (int j = 0; j < 8; j++) cs[j] = (j < rem) ? cs[j] : c0v;

        int myc = cs[lane & 7];
        float2 es2 = __ldg(&esrc2[myc]);
        float es = (lane >= 16) ? es2.y : es2.x;

        uint2 r[8];
#pragma unroll
        for (int j = 0; j < 8; j++)
            r[j] = __ldg(&h2[(size_t)cs[j] * 32 + lane]);

        float x  = es + ed;
        float lv = fminf(x > 0.f ? x : NEG_SLOPE * x, 80.f);
        float myp = ((lane & 7) < rem) ? __expf(lv) : 0.f;

#pragma unroll
        for (int j = 0; j < 8; j++) {
            float pj = __shfl_sync(0xffffffffu, myp, j, 16);
            float2 fa = __half22float2(*(__half2*)&r[j].x);
            float2 fb = __half22float2(*(__half2*)&r[j].y);
            s += pj;
            acc.x += pj * fa.x;
            acc.y += pj * fa.y;
            acc.z += pj * fb.x;
            acc.w += pj * fb.y;
        }
    }

    float inv = 1.f / (s + 1e-16f);
    float4 bv = __ldg(&((const float4*)bias)[lane]);
    float4 o;
    o.x = acc.x * inv + bv.x;
    o.y = acc.y * inv + bv.y;
    o.z = acc.z * inv + bv.z;
    o.w = acc.w * inv + bv.w;
    if (do_relu) {
        o.x = fmaxf(o.x, 0.f); o.y = fmaxf(o.y, 0.f);
        o.z = fmaxf(o.z, 0.f); o.w = fmaxf(o.w, 0.f);
    }
    ((float4*)out)[(size_t)d * 32 + lane] = o;
}

// ---------------- host side ----------------
static cudaStream_t s_csr = nullptr;
static cudaEvent_t  ev_fork = nullptr, ev_join = nullptr;

extern "C" void kernel_launch(void* const* d_in, const int* in_sizes, int n_in,
                              void* d_out, int out_size) {
    const float* x      = (const float*)d_in[0];
    const void*  ei     = d_in[1];
    const float* W_in   = (const float*)d_in[2];
    const float* as_in  = (const float*)d_in[3];
    const float* ad_in  = (const float*)d_in[4];
    const float* b_in   = (const float*)d_in[5];
    const float* W_h    = (const float*)d_in[6];
    const float* as_h   = (const float*)d_in[7];
    const float* ad_h   = (const float*)d_in[8];
    const float* b_h    = (const float*)d_in[9];
    const float* W_out  = (const float*)d_in[10];
    const float* as_out = (const float*)d_in[11];
    const float* ad_out = (const float*)d_in[12];
    const float* b_out  = (const float*)d_in[13];
    float* out = (float*)d_out;

    __half* p_h16 = nullptr;
    float*  p_x   = nullptr;
    cudaGetSymbolAddress((void**)&p_h16, g_h16);
    cudaGetSymbolAddress((void**)&p_x, g_x);

    if (!s_csr) {
        cudaStreamCreate(&s_csr);
        cudaEventCreateWithFlags(&ev_fork, cudaEventDisableTiming);
        cudaEventCreateWithFlags(&ev_join, cudaEventDisableTiming);
        cudaFuncSetAttribute(k_gemm_wmma_fused,
                             cudaFuncAttributeMaxDynamicSharedMemorySize, GEMM_SMEM);
    }

    const int eb = (N_EDGES + 255) / 256;
    const int nb = (N_NODES + 255) / 256;
    const int gemm_blocks = (N_NODES + 127) / 128;
    const int warp_blocks = (N_NODES * 32 + 255) / 256;

    // ---- fork: CSR build on side stream, layer-0 GEMM in parallel ----
    cudaEventRecord(ev_fork, 0);
    cudaStreamWaitEvent(s_csr, ev_fork, 0);
    k_init_detect<<<nb, 256, 0, s_csr>>>((const long long*)ei);
    k_convert_hist<<<eb, 256, 0, s_csr>>>(ei);
    k_scan1<<<SCAN_NBLK, SCAN_BLK, 0, s_csr>>>();
    k_scan3_selfloop<<<SCAN_NBLK, SCAN_BLK, 0, s_csr>>>();
    k_scatter<<<eb, 256, 0, s_csr>>>();
    cudaEventRecord(ev_join, s_csr);

    k_gemm_wmma_fused<<<gemm_blocks, 256, GEMM_SMEM>>>(x, W_in, p_h16, as_in, ad_in, N_NODES);

    cudaStreamWaitEvent(0, ev_join, 0);
    k_agg<<<warp_blocks, 256>>>(b_in, p_x, 1);

    k_gemm_wmma_fused<<<gemm_blocks, 256, GEMM_SMEM>>>(p_x, W_h, p_h16, as_h, ad_h, N_NODES);
    k_agg<<<warp_blocks, 256>>>(b_h, p_x, 1);

    k_gemm_wmma_fused<<<gemm_blocks, 256, GEMM_SMEM>>>(p_x, W_h + 128 * 128, p_h16,
                                                       as_h + 128, ad_h + 128, N_NODES);
    k_agg<<<warp_blocks, 256>>>(b_h + 128, p_x, 1);

    k_gemm_wmma_fused<<<gemm_blocks, 256, GEMM_SMEM>>>(p_x, W_out, p_h16, as_out, ad_out, N_NODES);
    k_agg<<<warp_blocks, 256>>>(b_out, out, 0);
}